// round 1
// baseline (speedup 1.0000x reference)
#include <cuda_runtime.h>
#include <math.h>

#define BATCH 4
#define CDIM  64
#define NPIX  6400
#define TILE  64
#define NT    (NPIX / TILE)   // 100
#define NTHREADS 256

// Scratch for projected (and pre-scaled) q, layout [b][n][c]
__device__ float g_q[BATCH * NPIX * CDIM];

// ---------------------------------------------------------------------------
// Kernel 1: q projection.  q[b][n][c] = scale * (sum_d Wq[c][d]*query[b][d][n] + bq[c])
// grid (NT, BATCH), block 256 (16x16, 4x4 microtile)
// ---------------------------------------------------------------------------
__global__ void qproj_kernel(const float* __restrict__ query,
                             const float* __restrict__ Wq,
                             const float* __restrict__ bq)
{
    __shared__ float wt[CDIM * CDIM];   // wt[d][c]  (Wq transposed)
    __shared__ float xs[CDIM * TILE];   // xs[d][n]

    const int b  = blockIdx.y;
    const int n0 = blockIdx.x * TILE;
    const int tid = threadIdx.x;

    // Load Wq transposed: Wq is [c][d] row-major
    for (int e = tid; e < CDIM * CDIM; e += NTHREADS) {
        int c = e >> 6, d = e & 63;
        wt[d * CDIM + c] = Wq[e];
    }
    // Load query tile: query[b][d][n0+n], coalesced over n
    const float* qbase = query + (size_t)b * CDIM * NPIX + n0;
    for (int e = tid; e < CDIM * TILE; e += NTHREADS) {
        int d = e >> 6, n = e & 63;
        xs[d * TILE + n] = qbase[(size_t)d * NPIX + n];
    }
    __syncthreads();

    const int ty = tid >> 4, tx = tid & 15;
    float acc[4][4] = {};

#pragma unroll 8
    for (int d = 0; d < CDIM; d++) {
        float4 xv = *(const float4*)&xs[d * TILE + 4 * ty];
        float4 wv = *(const float4*)&wt[d * CDIM + 4 * tx];
        float xa[4] = {xv.x, xv.y, xv.z, xv.w};
        float wa[4] = {wv.x, wv.y, wv.z, wv.w};
#pragma unroll
        for (int i = 0; i < 4; i++)
#pragma unroll
            for (int j = 0; j < 4; j++)
                acc[i][j] += xa[i] * wa[j];
    }

    const float scale = 0.125f;  // 64^-0.5
    float bj[4];
#pragma unroll
    for (int j = 0; j < 4; j++) bj[j] = bq[4 * tx + j];

#pragma unroll
    for (int i = 0; i < 4; i++) {
        int n = n0 + 4 * ty + i;
        float4 o;
        o.x = (acc[i][0] + bj[0]) * scale;
        o.y = (acc[i][1] + bj[1]) * scale;
        o.z = (acc[i][2] + bj[2]) * scale;
        o.w = (acc[i][3] + bj[3]) * scale;
        *(float4*)&g_q[((size_t)b * NPIX + n) * CDIM + 4 * tx] = o;
    }
}

// ---------------------------------------------------------------------------
// Kernel 2: fused flash attention over N=6400, head dim 64.
// grid (NT, BATCH), block 256 (16x16, 4x4 microtiles), dynamic smem.
// ---------------------------------------------------------------------------
__global__ void attn_kernel(const float* __restrict__ keys,
                            const float* __restrict__ values,
                            float* __restrict__ out)
{
    extern __shared__ float sm[];
    float* qs = sm;                    // q^T tile: qs[c*65 + r]   (stride 65, conflict-free)
    float* ks = qs + 64 * 65;          // K tile:   ks[c*64 + m]
    float* vt = ks + 64 * 64;          // V^T tile: vt[m*65 + c]   (stride 65)
    float* ps = vt + 64 * 65;          // P tile:   ps[r*64 + m]

    const int b  = blockIdx.y;
    const int r0 = blockIdx.x * TILE;
    const int tid = threadIdx.x;
    const int ty = tid >> 4, tx = tid & 15;

    // Load q tile transposed from scratch (coalesced over c, conflict-free smem writes)
    for (int e = tid; e < CDIM * TILE; e += NTHREADS) {
        int r = e >> 6, c = e & 63;
        qs[c * 65 + r] = g_q[((size_t)b * NPIX + r0 + r) * CDIM + c];
    }

    float o[4][4] = {};
    float mo[4] = {-INFINITY, -INFINITY, -INFINITY, -INFINITY};
    float l[4]  = {0.f, 0.f, 0.f, 0.f};

    const float* kb = keys   + (size_t)b * CDIM * NPIX;
    const float* vb = values + (size_t)b * CDIM * NPIX;

    for (int mt = 0; mt < NT; mt++) {
        __syncthreads();
        const int m0 = mt * TILE;
        // Load K tile [c][m] (natural) and V tile transposed [m][c] (stride-65,
        // conflict-free since consecutive threads hit consecutive m)
        for (int e = tid; e < CDIM * TILE; e += NTHREADS) {
            int c = e >> 6, m = e & 63;
            float kv = kb[(size_t)c * NPIX + m0 + m];
            float vv = vb[(size_t)c * NPIX + m0 + m];
            ks[c * 64 + m] = kv;
            vt[m * 65 + c] = vv;
        }
        __syncthreads();

        // GEMM1: S[r][m] = sum_c q[r][c] * k[c][m]   (q pre-scaled)
        float s[4][4] = {};
#pragma unroll 8
        for (int c = 0; c < CDIM; c++) {
            float4 kv = *(const float4*)&ks[c * 64 + 4 * tx];
            float ka[4] = {kv.x, kv.y, kv.z, kv.w};
            float qa[4];
#pragma unroll
            for (int i = 0; i < 4; i++) qa[i] = qs[c * 65 + 4 * ty + i];  // broadcast
#pragma unroll
            for (int i = 0; i < 4; i++)
#pragma unroll
                for (int j = 0; j < 4; j++)
                    s[i][j] += qa[i] * ka[j];
        }

        // Online softmax. Each row r = 4*ty+i is owned by the 16 lanes sharing ty.
        // (m,l) state is replicated across those lanes (identical arithmetic).
        float cf[4];
#pragma unroll
        for (int i = 0; i < 4; i++) {
            float tm = fmaxf(fmaxf(s[i][0], s[i][1]), fmaxf(s[i][2], s[i][3]));
#pragma unroll
            for (int off = 8; off >= 1; off >>= 1)
                tm = fmaxf(tm, __shfl_xor_sync(0xffffffffu, tm, off));
            float mn = fmaxf(mo[i], tm);
            float p0 = __expf(s[i][0] - mn);
            float p1 = __expf(s[i][1] - mn);
            float p2 = __expf(s[i][2] - mn);
            float p3 = __expf(s[i][3] - mn);
            float ts = (p0 + p1) + (p2 + p3);
#pragma unroll
            for (int off = 8; off >= 1; off >>= 1)
                ts += __shfl_xor_sync(0xffffffffu, ts, off);
            cf[i] = __expf(mo[i] - mn);
            l[i]  = l[i] * cf[i] + ts;
            mo[i] = mn;
            *(float4*)&ps[(4 * ty + i) * 64 + 4 * tx] = make_float4(p0, p1, p2, p3);
        }
        __syncthreads();

        // Rescale existing accumulator
#pragma unroll
        for (int i = 0; i < 4; i++)
#pragma unroll
            for (int j = 0; j < 4; j++)
                o[i][j] *= cf[i];

        // GEMM2: O[r][c] += sum_m P[r][m] * V[m][c]
#pragma unroll 8
        for (int m = 0; m < TILE; m++) {
            float va[4];
#pragma unroll
            for (int j = 0; j < 4; j++) va[j] = vt[m * 65 + 4 * tx + j];
            float pa[4];
#pragma unroll
            for (int i = 0; i < 4; i++) pa[i] = ps[(4 * ty + i) * 64 + m];  // broadcast
#pragma unroll
            for (int i = 0; i < 4; i++)
#pragma unroll
                for (int j = 0; j < 4; j++)
                    o[i][j] += pa[i] * va[j];
        }
    }

    // Normalize and stage output transposed through smem (reuse qs buffer) for
    // coalesced global writes: out[b][c][r0+r]
    __syncthreads();
    float inv[4];
#pragma unroll
    for (int i = 0; i < 4; i++) inv[i] = 1.0f / l[i];
#pragma unroll
    for (int i = 0; i < 4; i++)
#pragma unroll
        for (int j = 0; j < 4; j++)
            qs[(4 * tx + j) * 65 + 4 * ty + i] = o[i][j] * inv[i];
    __syncthreads();

    float* ob = out + (size_t)b * CDIM * NPIX + r0;
    for (int e = tid; e < CDIM * TILE; e += NTHREADS) {
        int c = e >> 6, r = e & 63;
        ob[(size_t)c * NPIX + r] = qs[c * 65 + r];
    }
}

// ---------------------------------------------------------------------------
extern "C" void kernel_launch(void* const* d_in, const int* in_sizes, int n_in,
                              void* d_out, int out_size)
{
    const float* query  = (const float*)d_in[0];
    const float* keys   = (const float*)d_in[1];
    const float* values = (const float*)d_in[2];
    const float* Wq     = (const float*)d_in[3];
    const float* bq     = (const float*)d_in[4];
    float* out = (float*)d_out;

    static bool attr_set = false;
    const int smem_bytes = (64 * 65 + 64 * 64 + 64 * 65 + 64 * 64) * sizeof(float); // 66048
    if (!attr_set) {
        cudaFuncSetAttribute(attn_kernel, cudaFuncAttributeMaxDynamicSharedMemorySize, smem_bytes);
        attr_set = true;
    }

    dim3 grid(NT, BATCH);
    qproj_kernel<<<grid, NTHREADS>>>(query, Wq, bq);
    attn_kernel<<<grid, NTHREADS, smem_bytes>>>(keys, values, out);
}